// round 1
// baseline (speedup 1.0000x reference)
#include <cuda_runtime.h>
#include <math.h>

#define NMAX 16000
#define EMAX 400000
#define HIDC 64
#define NHEADS 6
#define HC 384
#define NGMAX 16

// ---------------- scratch (static device globals: no allocation allowed) ---------
__device__ float g_h[NMAX * HIDC];
__device__ float g_xl[NMAX * HC];
__device__ float g_xr[NMAX * HC];
__device__ float g_ea[EMAX];
__device__ float g_alpha[EMAX * NHEADS];
__device__ int   g_deg[NMAX + 1];
__device__ int   g_rowptr[NMAX + 1];
__device__ int   g_cursor[NMAX];
__device__ int   g_csr[EMAX];
__device__ float g_mean[NGMAX * HIDC];
__device__ float g_istd[NGMAX * HIDC];

// ---------------- edge feature MLP: ea[e] = relu(relu(ew*w_e1+b_e1) @ w_e2 + b_e2)
__global__ void ea_kernel(const int* __restrict__ ei, const float* __restrict__ pos,
                          const float* __restrict__ w_e1, const float* __restrict__ b_e1,
                          const float* __restrict__ w_e2, const float* __restrict__ b_e2,
                          int E) {
    int e = blockIdx.x * 256 + threadIdx.x;
    if (e >= E) return;
    int s = ei[e], d = ei[E + e];
    float dx = pos[s * 3 + 0] - pos[d * 3 + 0];
    float dy = pos[s * 3 + 1] - pos[d * 3 + 1];
    float dz = pos[s * 3 + 2] - pos[d * 3 + 2];
    float ss = dx * dx + dy * dy + dz * dz;
    float ew = (ss == 0.f) ? 0.f : sqrtf(ss);
    float acc = b_e2[0];
#pragma unroll
    for (int j = 0; j < 32; j++) {
        float m = fmaxf(ew * w_e1[j] + b_e1[j], 0.f);
        acc += m * w_e2[j];
    }
    g_ea[e] = fmaxf(acc, 0.f);
}

// ---------------- h0 = x @ w_lin1 + b_lin1  (N x 32 @ 32 x 64)
__global__ void h0_kernel(const float* __restrict__ x, const float* __restrict__ w,
                          const float* __restrict__ b, int N) {
    int tid = threadIdx.x;
    int c = tid & 63;
    int n = blockIdx.x * 4 + (tid >> 6);
    if (n >= N) return;
    float acc = b[c];
    const float* xr = x + n * 32;
#pragma unroll
    for (int k = 0; k < 32; k++) acc += xr[k] * w[k * 64 + c];
    g_h[n * 64 + c] = acc;
}

// ---------------- CSR build ----------------
__global__ void zero_deg(int N) {
    int i = blockIdx.x * 256 + threadIdx.x;
    if (i <= N) g_deg[i] = 0;
}
__global__ void hist_kernel(const int* __restrict__ ei, int E) {
    int e = blockIdx.x * 256 + threadIdx.x;
    if (e < E) atomicAdd(&g_deg[ei[E + e]], 1);
}
__global__ void scan_kernel(int N) {
    __shared__ int ss[1024];
    int tid = threadIdx.x;
    int total = N + 1;
    int per = (total + 1023) / 1024;
    int b0 = tid * per;
    int b1 = min(b0 + per, total);
    int s = 0;
    for (int i = b0; i < b1; i++) s += g_deg[i];
    ss[tid] = s;
    __syncthreads();
    for (int off = 1; off < 1024; off <<= 1) {
        int add = (tid >= off) ? ss[tid - off] : 0;
        __syncthreads();
        ss[tid] += add;
        __syncthreads();
    }
    int run = ss[tid] - s;
    for (int i = b0; i < b1; i++) {
        g_rowptr[i] = run;
        if (i < N) g_cursor[i] = run;
        run += g_deg[i];
    }
}
__global__ void scatter_kernel(const int* __restrict__ ei, int E) {
    int e = blockIdx.x * 256 + threadIdx.x;
    if (e >= E) return;
    int d = ei[E + e];
    int p = atomicAdd(&g_cursor[d], 1);
    g_csr[p] = e;
}

// ---------------- GEMM: xl = h@Wl+bl, xr = h@Wr+br  (64-k, 384 cols each)
// grid.x: node tiles of 64, grid.y in [0,6): y<3 -> xl cols y*128, else xr
__global__ __launch_bounds__(256) void gemm_kernel(const float* __restrict__ Wl,
                                                   const float* __restrict__ bl,
                                                   const float* __restrict__ Wr,
                                                   const float* __restrict__ br, int N) {
    __shared__ float hs[64 * 64];   // hs[m*64+k]
    __shared__ float ws[64 * 128];  // ws[k*128+c]
    int tid = threadIdx.x;
    int nbase = blockIdx.x * 64;
    int y = blockIdx.y;
    const float* W;
    const float* b;
    float* outp;
    int colbase;
    if (y < 3) { W = Wl; b = bl; outp = g_xl; colbase = y * 128; }
    else       { W = Wr; b = br; outp = g_xr; colbase = (y - 3) * 128; }

    for (int idx = tid; idx < 64 * 64; idx += 256) {
        int gi = nbase * 64 + idx;
        hs[idx] = (gi < N * 64) ? g_h[gi] : 0.f;
    }
    for (int idx = tid; idx < 64 * 128; idx += 256) {
        int k = idx >> 7, c = idx & 127;
        ws[idx] = W[k * HC + colbase + c];
    }
    __syncthreads();

    int tc = tid & 31, tm = tid >> 5;
    float acc[8][4];
#pragma unroll
    for (int i = 0; i < 8; i++)
#pragma unroll
        for (int j = 0; j < 4; j++) acc[i][j] = 0.f;

#pragma unroll 4
    for (int k = 0; k < 64; k++) {
        float4 wv = *(const float4*)&ws[k * 128 + tc * 4];
#pragma unroll
        for (int i = 0; i < 8; i++) {
            float hv = hs[(tm * 8 + i) * 64 + k];  // broadcast within warp
            acc[i][0] += hv * wv.x;
            acc[i][1] += hv * wv.y;
            acc[i][2] += hv * wv.z;
            acc[i][3] += hv * wv.w;
        }
    }
    int cb = colbase + tc * 4;
    float4 bv = *(const float4*)&b[cb];
#pragma unroll
    for (int i = 0; i < 8; i++) {
        int n = nbase + tm * 8 + i;
        if (n < N) {
            float4 r;
            r.x = acc[i][0] + bv.x;
            r.y = acc[i][1] + bv.y;
            r.z = acc[i][2] + bv.z;
            r.w = acc[i][3] + bv.w;
            *(float4*)&outp[n * HC + cb] = r;
        }
    }
}

// ---------------- attention logits: one warp per edge
__global__ void alpha_kernel(const int* __restrict__ ei, int E,
                             const float* __restrict__ Wel, const float* __restrict__ attl) {
    int w = (blockIdx.x * blockDim.x + threadIdx.x) >> 5;
    int lane = threadIdx.x & 31;
    if (w >= E) return;
    int s = ei[w], d = ei[E + w];
    float eav = g_ea[w];
    const float* xls = g_xl + s * HC;
    const float* xrs = g_xr + d * HC;
#pragma unroll
    for (int h = 0; h < NHEADS; h++) {
        int c = h * 64 + lane;
        float a1 = xls[c] + xrs[c] + eav * Wel[c];
        a1 = (a1 > 0.f) ? a1 : 0.2f * a1;
        float a2 = xls[c + 32] + xrs[c + 32] + eav * Wel[c + 32];
        a2 = (a2 > 0.f) ? a2 : 0.2f * a2;
        float p = a1 * attl[c] + a2 * attl[c + 32];
        p += __shfl_xor_sync(0xffffffffu, p, 16);
        p += __shfl_xor_sync(0xffffffffu, p, 8);
        p += __shfl_xor_sync(0xffffffffu, p, 4);
        p += __shfl_xor_sync(0xffffffffu, p, 2);
        p += __shfl_xor_sync(0xffffffffu, p, 1);
        if (lane == 0) g_alpha[w * NHEADS + h] = p;
    }
}

// ---------------- softmax + aggregation: one warp per dst node (CSR, no float atomics)
__global__ void aggregate_kernel(const int* __restrict__ ei, int E,
                                 const float* __restrict__ bgl, int N) {
    int n = blockIdx.x * 8 + (threadIdx.x >> 5);
    int lane = threadIdx.x & 31;
    if (n >= N) return;
    int beg = g_rowptr[n], end = g_rowptr[n + 1];
    float amax[NHEADS];
#pragma unroll
    for (int h = 0; h < NHEADS; h++) amax[h] = -1e30f;
    for (int p = beg; p < end; p++) {
        int eid = g_csr[p];
#pragma unroll
        for (int h = 0; h < NHEADS; h++)
            amax[h] = fmaxf(amax[h], g_alpha[eid * NHEADS + h]);
    }
    float den[NHEADS];
    float acc[12];
#pragma unroll
    for (int h = 0; h < NHEADS; h++) den[h] = 0.f;
#pragma unroll
    for (int k = 0; k < 12; k++) acc[k] = 0.f;
    for (int p = beg; p < end; p++) {
        int eid = g_csr[p];
        int s = ei[eid];
        float ex[NHEADS];
#pragma unroll
        for (int h = 0; h < NHEADS; h++) {
            ex[h] = __expf(g_alpha[eid * NHEADS + h] - amax[h]);
            den[h] += ex[h];
        }
        const float* xs = g_xl + s * HC;
#pragma unroll
        for (int k = 0; k < 12; k++) acc[k] += ex[k >> 1] * xs[lane + 32 * k];
    }
    float o1 = 0.f, o2 = 0.f;
#pragma unroll
    for (int h = 0; h < NHEADS; h++) {
        float dv = den[h] + 1e-16f;
        o1 += acc[2 * h] / dv;
        o2 += acc[2 * h + 1] / dv;
    }
    int c1 = lane, c2 = lane + 32;
    float v1 = o1 * (1.f / 6.f) + bgl[c1];
    float v2 = o2 * (1.f / 6.f) + bgl[c2];
    g_h[n * 64 + c1] = fmaxf(g_h[n * 64 + c1] + v1, 0.f);
    g_h[n * 64 + c2] = fmaxf(g_h[n * 64 + c2] + v2, 0.f);
}

// ---------------- instance norm ----------------
__global__ void inorm_stats(int NP) {
    int g = blockIdx.x;
    int tid = threadIdx.x;
    int c = tid & 63, r = tid >> 6;
    float s = 0.f, s2 = 0.f;
    for (int i = r; i < NP; i += 4) {
        float v = g_h[(g * NP + i) * 64 + c];
        s += v;
        s2 += v * v;
    }
    __shared__ float sh[256], sh2[256];
    sh[tid] = s;
    sh2[tid] = s2;
    __syncthreads();
    if (r == 0) {
        float ts = sh[c] + sh[64 + c] + sh[128 + c] + sh[192 + c];
        float t2 = sh2[c] + sh2[64 + c] + sh2[128 + c] + sh2[192 + c];
        float mean = ts / NP;
        float var = fmaxf(t2 / NP - mean * mean, 0.f);
        g_mean[g * 64 + c] = mean;
        g_istd[g * 64 + c] = rsqrtf(var + 1e-5f);
    }
}
__global__ void inorm_apply(const int* __restrict__ batch, int N) {
    int idx = blockIdx.x * 256 + threadIdx.x;
    if (idx >= N * 64) return;
    int n = idx >> 6, c = idx & 63;
    int g = batch[n];
    g_h[idx] = (g_h[idx] - g_mean[g * 64 + c]) * g_istd[g * 64 + c];
}

// ---------------- final MLP head (z->bn1->h_out->bn2->pred) ----------------
__global__ __launch_bounds__(256) void final_kernel(
    const float* __restrict__ w_emb1, const float* __restrict__ b_emb1,
    const float* __restrict__ g1, const float* __restrict__ b1,
    const float* __restrict__ m1, const float* __restrict__ v1,
    const float* __restrict__ w_emb2, const float* __restrict__ b_emb2,
    const float* __restrict__ g2, const float* __restrict__ b2,
    const float* __restrict__ m2, const float* __restrict__ v2,
    const float* __restrict__ w_pred, const float* __restrict__ b_pred,
    float* __restrict__ out, int N) {
    __shared__ float hs[32 * 64];
    __shared__ float ws[64 * 64];
    __shared__ float zs[32 * 64];
    __shared__ float hos[32 * 64];
    __shared__ float sc1[64], sh1[64], sc2[64], sh2[64];
    int tid = threadIdx.x;
    int nbase = blockIdx.x * 32;
    if (tid < 64) {
        float s = g1[tid] * rsqrtf(v1[tid] + 1e-5f);
        sc1[tid] = s;
        sh1[tid] = b1[tid] - m1[tid] * s;
        float t = g2[tid] * rsqrtf(v2[tid] + 1e-5f);
        sc2[tid] = t;
        sh2[tid] = b2[tid] - m2[tid] * t;
    }
    for (int idx = tid; idx < 32 * 64; idx += 256) {
        int gi = nbase * 64 + idx;
        hs[idx] = (gi < N * 64) ? g_h[gi] : 0.f;
    }
    for (int idx = tid; idx < 64 * 64; idx += 256) ws[idx] = w_emb1[idx];
    __syncthreads();
    int c = tid & 63;
    int mg = (tid >> 6) * 8;
    float zv[8];
#pragma unroll
    for (int i = 0; i < 8; i++) {
        int m = mg + i;
        float acc = b_emb1[c];
#pragma unroll 4
        for (int k = 0; k < 64; k++) acc += hs[m * 64 + k] * ws[k * 64 + c];
        acc = fmaxf(acc, 0.f);
        zv[i] = acc * sc1[c] + sh1[c];
    }
    __syncthreads();
#pragma unroll
    for (int i = 0; i < 8; i++) zs[(mg + i) * 64 + c] = zv[i];
    for (int idx = tid; idx < 64 * 64; idx += 256) ws[idx] = w_emb2[idx];
    __syncthreads();
#pragma unroll
    for (int i = 0; i < 8; i++) {
        int m = mg + i;
        int n = nbase + m;
        float acc = b_emb2[c];
#pragma unroll 4
        for (int k = 0; k < 64; k++) acc += zs[m * 64 + k] * ws[k * 64 + c];
        if (n < N) out[n * 64 + c] = acc;
        hos[m * 64 + c] = acc * sc2[c] + sh2[c];
    }
    __syncthreads();
    if (tid < 32) {
        int n = nbase + tid;
        if (n < N) {
            float acc = b_pred[0];
#pragma unroll 4
            for (int k = 0; k < 64; k++) acc += hos[tid * 64 + k] * w_pred[k];
            out[N * 64 + n] = acc;
        }
    }
}

// ---------------- launch ----------------
extern "C" void kernel_launch(void* const* d_in, const int* in_sizes, int n_in,
                              void* d_out, int out_size) {
    const float* x      = (const float*)d_in[0];
    const float* pos    = (const float*)d_in[1];
    const float* w_lin1 = (const float*)d_in[2];
    const float* b_lin1 = (const float*)d_in[3];
    const float* w_e1   = (const float*)d_in[4];
    const float* b_e1   = (const float*)d_in[5];
    const float* w_e2   = (const float*)d_in[6];
    const float* b_e2   = (const float*)d_in[7];
    const float* Wl     = (const float*)d_in[8];
    const float* bl     = (const float*)d_in[9];
    const float* Wr     = (const float*)d_in[10];
    const float* br     = (const float*)d_in[11];
    const float* We     = (const float*)d_in[12];
    const float* att    = (const float*)d_in[13];
    const float* b_gat  = (const float*)d_in[14];
    const float* w_emb1 = (const float*)d_in[15];
    const float* b_emb1 = (const float*)d_in[16];
    const float* bn1_g  = (const float*)d_in[17];
    const float* bn1_b  = (const float*)d_in[18];
    const float* bn1_m  = (const float*)d_in[19];
    const float* bn1_v  = (const float*)d_in[20];
    const float* w_emb2 = (const float*)d_in[21];
    const float* b_emb2 = (const float*)d_in[22];
    const float* bn2_g  = (const float*)d_in[23];
    const float* bn2_b  = (const float*)d_in[24];
    const float* bn2_m  = (const float*)d_in[25];
    const float* bn2_v  = (const float*)d_in[26];
    const float* w_pred = (const float*)d_in[27];
    const float* b_pred = (const float*)d_in[28];
    const int*   ei     = (const int*)d_in[29];
    const int*   batch  = (const int*)d_in[30];
    float* out = (float*)d_out;

    int N = in_sizes[0] / 32;
    int E = in_sizes[29] / 2;
    int NG = 16;
    int NP = N / NG;

    // edge features + h0 + CSR build
    ea_kernel<<<(E + 255) / 256, 256>>>(ei, pos, w_e1, b_e1, w_e2, b_e2, E);
    h0_kernel<<<(N + 3) / 4, 256>>>(x, w_lin1, b_lin1, N);
    zero_deg<<<(N + 256) / 256, 256>>>(N);
    hist_kernel<<<(E + 255) / 256, 256>>>(ei, E);
    scan_kernel<<<1, 1024>>>(N);
    scatter_kernel<<<(E + 255) / 256, 256>>>(ei, E);

    for (int i = 0; i < 4; i++) {
        const float* Wli = Wl + i * 64 * HC;
        const float* bli = bl + i * HC;
        const float* Wri = Wr + i * 64 * HC;
        const float* bri = br + i * HC;
        const float* Wei = We + i * HC;
        const float* atti = att + i * HC;
        const float* bgi = b_gat + i * 64;

        dim3 ggrid((N + 63) / 64, 6);
        gemm_kernel<<<ggrid, 256>>>(Wli, bli, Wri, bri, N);
        alpha_kernel<<<(E + 7) / 8, 256>>>(ei, E, Wei, atti);
        aggregate_kernel<<<(N + 7) / 8, 256>>>(ei, E, bgi, N);
        inorm_stats<<<NG, 256>>>(NP);
        inorm_apply<<<(N * 64 + 255) / 256, 256>>>(batch, N);
    }

    final_kernel<<<(N + 31) / 32, 256>>>(w_emb1, b_emb1, bn1_g, bn1_b, bn1_m, bn1_v,
                                         w_emb2, b_emb2, bn2_g, bn2_b, bn2_m, bn2_v,
                                         w_pred, b_pred, out, N);
}

// round 2
// speedup vs baseline: 2.2698x; 2.2698x over previous
#include <cuda_runtime.h>
#include <math.h>

#define NMAX 16000
#define EMAX 400000
#define HIDC 64
#define NHEADS 6
#define HC 384
#define NGMAX 16

// ---------------- scratch (static device globals: no allocation allowed) ---------
__device__ float g_h[NMAX * HIDC];
__device__ float g_xl[NMAX * HC];
__device__ float g_xr[NMAX * HC];
__device__ float g_ea[EMAX];
__device__ int   g_deg[NMAX + 1];
__device__ int   g_rowptr[NMAX + 1];
__device__ int   g_cursor[NMAX];
__device__ int   g_csr[EMAX];
__device__ float g_mean[NGMAX * HIDC];
__device__ float g_istd[NGMAX * HIDC];

// ---------------- edge feature MLP: ea[e] = relu(relu(ew*w_e1+b_e1) @ w_e2 + b_e2)
__global__ void ea_kernel(const int* __restrict__ ei, const float* __restrict__ pos,
                          const float* __restrict__ w_e1, const float* __restrict__ b_e1,
                          const float* __restrict__ w_e2, const float* __restrict__ b_e2,
                          int E) {
    int e = blockIdx.x * 256 + threadIdx.x;
    if (e >= E) return;
    int s = ei[e], d = ei[E + e];
    float dx = pos[s * 3 + 0] - pos[d * 3 + 0];
    float dy = pos[s * 3 + 1] - pos[d * 3 + 1];
    float dz = pos[s * 3 + 2] - pos[d * 3 + 2];
    float ss = dx * dx + dy * dy + dz * dz;
    float ew = (ss == 0.f) ? 0.f : sqrtf(ss);
    float acc = b_e2[0];
#pragma unroll
    for (int j = 0; j < 32; j++) {
        float m = fmaxf(ew * w_e1[j] + b_e1[j], 0.f);
        acc += m * w_e2[j];
    }
    g_ea[e] = fmaxf(acc, 0.f);
}

// ---------------- h0 = x @ w_lin1 + b_lin1  (N x 32 @ 32 x 64)
__global__ void h0_kernel(const float* __restrict__ x, const float* __restrict__ w,
                          const float* __restrict__ b, int N) {
    int tid = threadIdx.x;
    int c = tid & 63;
    int n = blockIdx.x * 4 + (tid >> 6);
    if (n >= N) return;
    float acc = b[c];
    const float* xr = x + n * 32;
#pragma unroll
    for (int k = 0; k < 32; k++) acc += xr[k] * w[k * 64 + c];
    g_h[n * 64 + c] = acc;
}

// ---------------- CSR build ----------------
__global__ void zero_deg(int N) {
    int i = blockIdx.x * 256 + threadIdx.x;
    if (i <= N) g_deg[i] = 0;
}
__global__ void hist_kernel(const int* __restrict__ ei, int E) {
    int e = blockIdx.x * 256 + threadIdx.x;
    if (e < E) atomicAdd(&g_deg[ei[E + e]], 1);
}
__global__ void scan_kernel(int N) {
    __shared__ int ss[1024];
    int tid = threadIdx.x;
    int total = N + 1;
    int per = (total + 1023) / 1024;
    int b0 = tid * per;
    int b1 = min(b0 + per, total);
    int s = 0;
    for (int i = b0; i < b1; i++) s += g_deg[i];
    ss[tid] = s;
    __syncthreads();
    for (int off = 1; off < 1024; off <<= 1) {
        int add = (tid >= off) ? ss[tid - off] : 0;
        __syncthreads();
        ss[tid] += add;
        __syncthreads();
    }
    int run = ss[tid] - s;
    for (int i = b0; i < b1; i++) {
        g_rowptr[i] = run;
        if (i < N) g_cursor[i] = run;
        run += g_deg[i];
    }
}
__global__ void scatter_kernel(const int* __restrict__ ei, int E) {
    int e = blockIdx.x * 256 + threadIdx.x;
    if (e >= E) return;
    int d = ei[E + e];
    int p = atomicAdd(&g_cursor[d], 1);
    g_csr[p] = e;
}

// ---------------- GEMM: xl = h@Wl+bl, xr = h@Wr+br  (64-k, 384 cols each)
// grid.x: node tiles of 64, grid.y in [0,6): y<3 -> xl cols y*128, else xr
__global__ __launch_bounds__(256) void gemm_kernel(const float* __restrict__ Wl,
                                                   const float* __restrict__ bl,
                                                   const float* __restrict__ Wr,
                                                   const float* __restrict__ br, int N) {
    __shared__ float hs[64 * 64];   // hs[m*64+k]
    __shared__ float ws[64 * 128];  // ws[k*128+c]
    int tid = threadIdx.x;
    int nbase = blockIdx.x * 64;
    int y = blockIdx.y;
    const float* W;
    const float* b;
    float* outp;
    int colbase;
    if (y < 3) { W = Wl; b = bl; outp = g_xl; colbase = y * 128; }
    else       { W = Wr; b = br; outp = g_xr; colbase = (y - 3) * 128; }

    for (int idx = tid; idx < 64 * 64; idx += 256) {
        int gi = nbase * 64 + idx;
        hs[idx] = (gi < N * 64) ? g_h[gi] : 0.f;
    }
    for (int idx = tid; idx < 64 * 128; idx += 256) {
        int k = idx >> 7, c = idx & 127;
        ws[idx] = W[k * HC + colbase + c];
    }
    __syncthreads();

    int tc = tid & 31, tm = tid >> 5;
    float acc[8][4];
#pragma unroll
    for (int i = 0; i < 8; i++)
#pragma unroll
        for (int j = 0; j < 4; j++) acc[i][j] = 0.f;

#pragma unroll 4
    for (int k = 0; k < 64; k++) {
        float4 wv = *(const float4*)&ws[k * 128 + tc * 4];
#pragma unroll
        for (int i = 0; i < 8; i++) {
            float hv = hs[(tm * 8 + i) * 64 + k];  // broadcast within warp
            acc[i][0] += hv * wv.x;
            acc[i][1] += hv * wv.y;
            acc[i][2] += hv * wv.z;
            acc[i][3] += hv * wv.w;
        }
    }
    int cb = colbase + tc * 4;
    float4 bv = *(const float4*)&b[cb];
#pragma unroll
    for (int i = 0; i < 8; i++) {
        int n = nbase + tm * 8 + i;
        if (n < N) {
            float4 r;
            r.x = acc[i][0] + bv.x;
            r.y = acc[i][1] + bv.y;
            r.z = acc[i][2] + bv.z;
            r.w = acc[i][3] + bv.w;
            *(float4*)&outp[n * HC + cb] = r;
        }
    }
}

// ---------------- fused GATv2: logits + online softmax + aggregation
// One warp per dst node. Lane l holds float4 columns {4l+128j : j=0..2}.
// Each float4 lies entirely inside one head: head(j,l) = 2j + (l>>4).
// Within-head partial dot reduces over the 16-lane group (xor 1,2,4,8).
__global__ __launch_bounds__(256) void gat_agg_kernel(const int* __restrict__ ei, int E,
                                                      const float* __restrict__ Wel,
                                                      const float* __restrict__ attl,
                                                      const float* __restrict__ bgl, int N) {
    int n = blockIdx.x * 8 + (threadIdx.x >> 5);
    int lane = threadIdx.x & 31;
    if (n >= N) return;
    int beg = g_rowptr[n], end = g_rowptr[n + 1];

    int col0 = 4 * lane;  // + 128*j
    float4 xr4[3], we4[3], at4[3];
#pragma unroll
    for (int j = 0; j < 3; j++) {
        xr4[j] = *(const float4*)&g_xr[n * HC + col0 + 128 * j];
        we4[j] = *(const float4*)&Wel[col0 + 128 * j];
        at4[j] = *(const float4*)&attl[col0 + 128 * j];
    }

    float m[3], den[3];
    float4 acc[3];
#pragma unroll
    for (int j = 0; j < 3; j++) {
        m[j] = -1e30f;
        den[j] = 0.f;
        acc[j] = make_float4(0.f, 0.f, 0.f, 0.f);
    }

    // prefetch first edge
    int eid = g_csr[beg];
    int s = ei[eid];
    float eav = g_ea[eid];
    float4 xl4[3];
#pragma unroll
    for (int j = 0; j < 3; j++)
        xl4[j] = *(const float4*)&g_xl[s * HC + col0 + 128 * j];

    for (int p = beg; p < end; p++) {
        float4 cur[3];
        float ceav = eav;
#pragma unroll
        for (int j = 0; j < 3; j++) cur[j] = xl4[j];
        if (p + 1 < end) {  // prefetch next edge (hide L2 latency behind reduce)
            eid = g_csr[p + 1];
            s = ei[eid];
            eav = g_ea[eid];
#pragma unroll
            for (int j = 0; j < 3; j++)
                xl4[j] = *(const float4*)&g_xl[s * HC + col0 + 128 * j];
        }

        float pd[3];
#pragma unroll
        for (int j = 0; j < 3; j++) {
            float gx = cur[j].x + xr4[j].x + ceav * we4[j].x;
            float gy = cur[j].y + xr4[j].y + ceav * we4[j].y;
            float gz = cur[j].z + xr4[j].z + ceav * we4[j].z;
            float gw = cur[j].w + xr4[j].w + ceav * we4[j].w;
            gx = (gx > 0.f) ? gx : 0.2f * gx;
            gy = (gy > 0.f) ? gy : 0.2f * gy;
            gz = (gz > 0.f) ? gz : 0.2f * gz;
            gw = (gw > 0.f) ? gw : 0.2f * gw;
            pd[j] = gx * at4[j].x + gy * at4[j].y + gz * at4[j].z + gw * at4[j].w;
        }
        // reduce within 16-lane head groups (xor 1,2,4,8 stays inside the group)
#pragma unroll
        for (int j = 0; j < 3; j++) {
            pd[j] += __shfl_xor_sync(0xffffffffu, pd[j], 1);
            pd[j] += __shfl_xor_sync(0xffffffffu, pd[j], 2);
            pd[j] += __shfl_xor_sync(0xffffffffu, pd[j], 4);
            pd[j] += __shfl_xor_sync(0xffffffffu, pd[j], 8);
        }
        // online softmax update (uniform across each 16-lane group)
#pragma unroll
        for (int j = 0; j < 3; j++) {
            float a = pd[j];
            float ex;
            if (a > m[j]) {
                float sc = __expf(m[j] - a);
                den[j] *= sc;
                acc[j].x *= sc;
                acc[j].y *= sc;
                acc[j].z *= sc;
                acc[j].w *= sc;
                m[j] = a;
                ex = 1.f;
            } else {
                ex = __expf(a - m[j]);
            }
            den[j] += ex;
            acc[j].x += ex * cur[j].x;
            acc[j].y += ex * cur[j].y;
            acc[j].z += ex * cur[j].z;
            acc[j].w += ex * cur[j].w;
        }
    }

    // normalize per head, sum the 3 heads this lane holds
    float4 sum = make_float4(0.f, 0.f, 0.f, 0.f);
#pragma unroll
    for (int j = 0; j < 3; j++) {
        float inv = 1.f / (den[j] + 1e-16f);
        sum.x += acc[j].x * inv;
        sum.y += acc[j].y * inv;
        sum.z += acc[j].z * inv;
        sum.w += acc[j].w * inv;
    }
    // pair with lane^16 to combine all 6 heads (within-head col = 4*(lane&15))
    sum.x += __shfl_xor_sync(0xffffffffu, sum.x, 16);
    sum.y += __shfl_xor_sync(0xffffffffu, sum.y, 16);
    sum.z += __shfl_xor_sync(0xffffffffu, sum.z, 16);
    sum.w += __shfl_xor_sync(0xffffffffu, sum.w, 16);

    if (lane < 16) {
        int c = 4 * lane;
        float4 hv = *(float4*)&g_h[n * 64 + c];
        float4 bv = *(const float4*)&bgl[c];
        float4 r;
        r.x = fmaxf(hv.x + sum.x * (1.f / 6.f) + bv.x, 0.f);
        r.y = fmaxf(hv.y + sum.y * (1.f / 6.f) + bv.y, 0.f);
        r.z = fmaxf(hv.z + sum.z * (1.f / 6.f) + bv.z, 0.f);
        r.w = fmaxf(hv.w + sum.w * (1.f / 6.f) + bv.w, 0.f);
        *(float4*)&g_h[n * 64 + c] = r;
    }
}

// ---------------- instance norm ----------------
__global__ void inorm_stats(int NP) {
    int g = blockIdx.x;
    int tid = threadIdx.x;
    int c = tid & 63, r = tid >> 6;
    float s = 0.f, s2 = 0.f;
    for (int i = r; i < NP; i += 4) {
        float v = g_h[(g * NP + i) * 64 + c];
        s += v;
        s2 += v * v;
    }
    __shared__ float sh[256], sh2[256];
    sh[tid] = s;
    sh2[tid] = s2;
    __syncthreads();
    if (r == 0) {
        float ts = sh[c] + sh[64 + c] + sh[128 + c] + sh[192 + c];
        float t2 = sh2[c] + sh2[64 + c] + sh2[128 + c] + sh2[192 + c];
        float mean = ts / NP;
        float var = fmaxf(t2 / NP - mean * mean, 0.f);
        g_mean[g * 64 + c] = mean;
        g_istd[g * 64 + c] = rsqrtf(var + 1e-5f);
    }
}
__global__ void inorm_apply(const int* __restrict__ batch, int N) {
    int idx = blockIdx.x * 256 + threadIdx.x;
    if (idx >= N * 64) return;
    int n = idx >> 6, c = idx & 63;
    int g = batch[n];
    g_h[idx] = (g_h[idx] - g_mean[g * 64 + c]) * g_istd[g * 64 + c];
}

// ---------------- final MLP head (z->bn1->h_out->bn2->pred) ----------------
__global__ __launch_bounds__(256) void final_kernel(
    const float* __restrict__ w_emb1, const float* __restrict__ b_emb1,
    const float* __restrict__ g1, const float* __restrict__ b1,
    const float* __restrict__ m1, const float* __restrict__ v1,
    const float* __restrict__ w_emb2, const float* __restrict__ b_emb2,
    const float* __restrict__ g2, const float* __restrict__ b2,
    const float* __restrict__ m2, const float* __restrict__ v2,
    const float* __restrict__ w_pred, const float* __restrict__ b_pred,
    float* __restrict__ out, int N) {
    __shared__ float hs[32 * 64];
    __shared__ float ws[64 * 64];
    __shared__ float zs[32 * 64];
    __shared__ float hos[32 * 64];
    __shared__ float sc1[64], sh1[64], sc2[64], sh2[64];
    int tid = threadIdx.x;
    int nbase = blockIdx.x * 32;
    if (tid < 64) {
        float s = g1[tid] * rsqrtf(v1[tid] + 1e-5f);
        sc1[tid] = s;
        sh1[tid] = b1[tid] - m1[tid] * s;
        float t = g2[tid] * rsqrtf(v2[tid] + 1e-5f);
        sc2[tid] = t;
        sh2[tid] = b2[tid] - m2[tid] * t;
    }
    for (int idx = tid; idx < 32 * 64; idx += 256) {
        int gi = nbase * 64 + idx;
        hs[idx] = (gi < N * 64) ? g_h[gi] : 0.f;
    }
    for (int idx = tid; idx < 64 * 64; idx += 256) ws[idx] = w_emb1[idx];
    __syncthreads();
    int c = tid & 63;
    int mg = (tid >> 6) * 8;
    float zv[8];
#pragma unroll
    for (int i = 0; i < 8; i++) {
        int m = mg + i;
        float acc = b_emb1[c];
#pragma unroll 4
        for (int k = 0; k < 64; k++) acc += hs[m * 64 + k] * ws[k * 64 + c];
        acc = fmaxf(acc, 0.f);
        zv[i] = acc * sc1[c] + sh1[c];
    }
    __syncthreads();
#pragma unroll
    for (int i = 0; i < 8; i++) zs[(mg + i) * 64 + c] = zv[i];
    for (int idx = tid; idx < 64 * 64; idx += 256) ws[idx] = w_emb2[idx];
    __syncthreads();
#pragma unroll
    for (int i = 0; i < 8; i++) {
        int m = mg + i;
        int n = nbase + m;
        float acc = b_emb2[c];
#pragma unroll 4
        for (int k = 0; k < 64; k++) acc += zs[m * 64 + k] * ws[k * 64 + c];
        if (n < N) out[n * 64 + c] = acc;
        hos[m * 64 + c] = acc * sc2[c] + sh2[c];
    }
    __syncthreads();
    if (tid < 32) {
        int n = nbase + tid;
        if (n < N) {
            float acc = b_pred[0];
#pragma unroll 4
            for (int k = 0; k < 64; k++) acc += hos[tid * 64 + k] * w_pred[k];
            out[N * 64 + n] = acc;
        }
    }
}

// ---------------- launch ----------------
extern "C" void kernel_launch(void* const* d_in, const int* in_sizes, int n_in,
                              void* d_out, int out_size) {
    const float* x      = (const float*)d_in[0];
    const float* pos    = (const float*)d_in[1];
    const float* w_lin1 = (const float*)d_in[2];
    const float* b_lin1 = (const float*)d_in[3];
    const float* w_e1   = (const float*)d_in[4];
    const float* b_e1   = (const float*)d_in[5];
    const float* w_e2   = (const float*)d_in[6];
    const float* b_e2   = (const float*)d_in[7];
    const float* Wl     = (const float*)d_in[8];
    const float* bl     = (const float*)d_in[9];
    const float* Wr     = (const float*)d_in[10];
    const float* br     = (const float*)d_in[11];
    const float* We     = (const float*)d_in[12];
    const float* att    = (const float*)d_in[13];
    const float* b_gat  = (const float*)d_in[14];
    const float* w_emb1 = (const float*)d_in[15];
    const float* b_emb1 = (const float*)d_in[16];
    const float* bn1_g  = (const float*)d_in[17];
    const float* bn1_b  = (const float*)d_in[18];
    const float* bn1_m  = (const float*)d_in[19];
    const float* bn1_v  = (const float*)d_in[20];
    const float* w_emb2 = (const float*)d_in[21];
    const float* b_emb2 = (const float*)d_in[22];
    const float* bn2_g  = (const float*)d_in[23];
    const float* bn2_b  = (const float*)d_in[24];
    const float* bn2_m  = (const float*)d_in[25];
    const float* bn2_v  = (const float*)d_in[26];
    const float* w_pred = (const float*)d_in[27];
    const float* b_pred = (const float*)d_in[28];
    const int*   ei     = (const int*)d_in[29];
    const int*   batch  = (const int*)d_in[30];
    float* out = (float*)d_out;

    int N = in_sizes[0] / 32;
    int E = in_sizes[29] / 2;
    int NG = 16;
    int NP = N / NG;

    // edge features + h0 + CSR build
    ea_kernel<<<(E + 255) / 256, 256>>>(ei, pos, w_e1, b_e1, w_e2, b_e2, E);
    h0_kernel<<<(N + 3) / 4, 256>>>(x, w_lin1, b_lin1, N);
    zero_deg<<<(N + 256) / 256, 256>>>(N);
    hist_kernel<<<(E + 255) / 256, 256>>>(ei, E);
    scan_kernel<<<1, 1024>>>(N);
    scatter_kernel<<<(E + 255) / 256, 256>>>(ei, E);

    for (int i = 0; i < 4; i++) {
        const float* Wli = Wl + i * 64 * HC;
        const float* bli = bl + i * HC;
        const float* Wri = Wr + i * 64 * HC;
        const float* bri = br + i * HC;
        const float* Wei = We + i * HC;
        const float* atti = att + i * HC;
        const float* bgi = b_gat + i * 64;

        dim3 ggrid((N + 63) / 64, 6);
        gemm_kernel<<<ggrid, 256>>>(Wli, bli, Wri, bri, N);
        gat_agg_kernel<<<(N + 7) / 8, 256>>>(ei, E, Wei, atti, bgi, N);
        inorm_stats<<<NG, 256>>>(NP);
        inorm_apply<<<(N * 64 + 255) / 256, 256>>>(batch, N);
    }

    final_kernel<<<(N + 31) / 32, 256>>>(w_emb1, b_emb1, bn1_g, bn1_b, bn1_m, bn1_v,
                                         w_emb2, b_emb2, bn2_g, bn2_b, bn2_m, bn2_v,
                                         w_pred, b_pred, out, N);
}

// round 3
// speedup vs baseline: 2.3465x; 1.0338x over previous
#include <cuda_runtime.h>
#include <math.h>
#include <stdint.h>

#define NMAX 16000
#define EMAX 400000
#define HIDC 64
#define NHEADS 6
#define HC 384
#define NGMAX 16

// ---------------- scratch (static device globals: no allocation allowed) ---------
__device__ float g_h[NMAX * HIDC];
__device__ float g_xl[NMAX * HC];
__device__ float g_xr[NMAX * HC];
__device__ float g_ea[EMAX];
__device__ int   g_deg[NMAX + 1];
__device__ int   g_rowptr[NMAX + 1];
__device__ int   g_cursor[NMAX];
__device__ int   g_csr[EMAX];
__device__ float g_mean[NGMAX * HIDC];
__device__ float g_istd[NGMAX * HIDC];

__device__ __forceinline__ uint32_t f2tf32(float v) {
    uint32_t u;
    asm("cvt.rna.tf32.f32 %0, %1;" : "=r"(u) : "f"(v));
    return u;
}

// ---------------- edge feature MLP ----------------
__global__ void ea_kernel(const int* __restrict__ ei, const float* __restrict__ pos,
                          const float* __restrict__ w_e1, const float* __restrict__ b_e1,
                          const float* __restrict__ w_e2, const float* __restrict__ b_e2,
                          int E) {
    int e = blockIdx.x * 256 + threadIdx.x;
    if (e >= E) return;
    int s = ei[e], d = ei[E + e];
    float dx = pos[s * 3 + 0] - pos[d * 3 + 0];
    float dy = pos[s * 3 + 1] - pos[d * 3 + 1];
    float dz = pos[s * 3 + 2] - pos[d * 3 + 2];
    float ss = dx * dx + dy * dy + dz * dz;
    float ew = (ss == 0.f) ? 0.f : sqrtf(ss);
    float acc = b_e2[0];
#pragma unroll
    for (int j = 0; j < 32; j++) {
        float m = fmaxf(ew * w_e1[j] + b_e1[j], 0.f);
        acc += m * w_e2[j];
    }
    g_ea[e] = fmaxf(acc, 0.f);
}

// ---------------- h0 = x @ w_lin1 + b_lin1 ----------------
__global__ void h0_kernel(const float* __restrict__ x, const float* __restrict__ w,
                          const float* __restrict__ b, int N) {
    int tid = threadIdx.x;
    int c = tid & 63;
    int n = blockIdx.x * 4 + (tid >> 6);
    if (n >= N) return;
    float acc = b[c];
    const float* xr = x + n * 32;
#pragma unroll
    for (int k = 0; k < 32; k++) acc += xr[k] * w[k * 64 + c];
    g_h[n * 64 + c] = acc;
}

// ---------------- CSR build ----------------
__global__ void zero_deg(int N) {
    int i = blockIdx.x * 256 + threadIdx.x;
    if (i <= N) g_deg[i] = 0;
}
__global__ void hist_kernel(const int* __restrict__ ei, int E) {
    int e = blockIdx.x * 256 + threadIdx.x;
    if (e < E) atomicAdd(&g_deg[ei[E + e]], 1);
}
__global__ void scan_kernel(int N) {
    __shared__ int ss[1024];
    int tid = threadIdx.x;
    int total = N + 1;
    int per = (total + 1023) / 1024;
    int b0 = tid * per;
    int b1 = min(b0 + per, total);
    int s = 0;
    for (int i = b0; i < b1; i++) s += g_deg[i];
    ss[tid] = s;
    __syncthreads();
    for (int off = 1; off < 1024; off <<= 1) {
        int add = (tid >= off) ? ss[tid - off] : 0;
        __syncthreads();
        ss[tid] += add;
        __syncthreads();
    }
    int run = ss[tid] - s;
    for (int i = b0; i < b1; i++) {
        g_rowptr[i] = run;
        if (i < N) g_cursor[i] = run;
        run += g_deg[i];
    }
}
__global__ void scatter_kernel(const int* __restrict__ ei, int E) {
    int e = blockIdx.x * 256 + threadIdx.x;
    if (e >= E) return;
    int d = ei[E + e];
    int p = atomicAdd(&g_cursor[d], 1);
    g_csr[p] = e;
}

// ---------------- tensor-core GEMM (tf32 mma.sync): xl = h@Wl+bl, xr = h@Wr+br
// grid.x: node tiles of 64; grid.y in [0,12): y<6 -> xl strip y*64, else xr strip.
// Block: 256 thr = 8 warps in a 4x2 grid; warp = 16 rows x 32 cols = 4 n-tiles m16n8k8.
#define HSTR 68
#define WSTR 76
__global__ __launch_bounds__(256) void gemm_tc_kernel(const float* __restrict__ Wl,
                                                      const float* __restrict__ bl,
                                                      const float* __restrict__ Wr,
                                                      const float* __restrict__ br, int N) {
    __shared__ uint32_t hs[64 * HSTR];   // hs[m*HSTR+k], tf32 bits
    __shared__ uint32_t ws[64 * WSTR];   // ws[c*WSTR+k]  (W^T), tf32 bits
    int tid = threadIdx.x;
    int nbase = blockIdx.x * 64;
    int y = blockIdx.y;
    const float* W;
    const float* b;
    float* outp;
    int colbase;
    if (y < 6) { W = Wl; b = bl; outp = g_xl; colbase = y * 64; }
    else       { W = Wr; b = br; outp = g_xr; colbase = (y - 6) * 64; }

    for (int idx = tid; idx < 64 * 64; idx += 256) {
        int m = idx >> 6, k = idx & 63;
        int n = nbase + m;
        float v = (n < N) ? g_h[n * 64 + k] : 0.f;
        hs[m * HSTR + k] = f2tf32(v);
    }
    for (int idx = tid; idx < 64 * 64; idx += 256) {
        int k = idx >> 6, c = idx & 63;  // coalesced global read over c
        ws[c * WSTR + k] = f2tf32(W[k * HC + colbase + c]);
    }
    __syncthreads();

    int w = tid >> 5, lane = tid & 31;
    int mb = (w & 3) * 16;        // warp row base within tile
    int cb = (w >> 2) * 32;       // warp col base within 64-col strip
    int g = lane >> 2, tig = lane & 3;

    float c0[4], c1[4], c2[4], c3[4];
#pragma unroll
    for (int nt = 0; nt < 4; nt++) { c0[nt] = c1[nt] = c2[nt] = c3[nt] = 0.f; }

#pragma unroll
    for (int k0 = 0; k0 < 64; k0 += 8) {
        uint32_t a0 = hs[(mb + g) * HSTR + k0 + tig];
        uint32_t a1 = hs[(mb + g + 8) * HSTR + k0 + tig];
        uint32_t a2 = hs[(mb + g) * HSTR + k0 + tig + 4];
        uint32_t a3 = hs[(mb + g + 8) * HSTR + k0 + tig + 4];
#pragma unroll
        for (int nt = 0; nt < 4; nt++) {
            uint32_t b0 = ws[(cb + nt * 8 + g) * WSTR + k0 + tig];
            uint32_t b1 = ws[(cb + nt * 8 + g) * WSTR + k0 + tig + 4];
            asm volatile(
                "mma.sync.aligned.m16n8k8.row.col.f32.tf32.tf32.f32 "
                "{%0,%1,%2,%3}, {%4,%5,%6,%7}, {%8,%9}, {%0,%1,%2,%3};"
                : "+f"(c0[nt]), "+f"(c1[nt]), "+f"(c2[nt]), "+f"(c3[nt])
                : "r"(a0), "r"(a1), "r"(a2), "r"(a3), "r"(b0), "r"(b1));
        }
    }

    // epilogue: C frag (m16n8): rows g / g+8, cols 2*tig, 2*tig+1 within n-tile
    int r0 = nbase + mb + g;
    int r1 = r0 + 8;
#pragma unroll
    for (int nt = 0; nt < 4; nt++) {
        int col = colbase + cb + nt * 8 + 2 * tig;
        float bx = b[col], by = b[col + 1];
        if (r0 < N) {
            float2 v = make_float2(c0[nt] + bx, c1[nt] + by);
            *(float2*)&outp[r0 * HC + col] = v;
        }
        if (r1 < N) {
            float2 v = make_float2(c2[nt] + bx, c3[nt] + by);
            *(float2*)&outp[r1 * HC + col] = v;
        }
    }
}

// ---------------- fused GATv2: logits + online softmax + aggregation
__global__ __launch_bounds__(256) void gat_agg_kernel(const int* __restrict__ ei, int E,
                                                      const float* __restrict__ Wel,
                                                      const float* __restrict__ attl,
                                                      const float* __restrict__ bgl, int N) {
    int n = blockIdx.x * 8 + (threadIdx.x >> 5);
    int lane = threadIdx.x & 31;
    if (n >= N) return;
    int beg = g_rowptr[n], end = g_rowptr[n + 1];

    int col0 = 4 * lane;  // + 128*j
    float4 xr4[3], we4[3], at4[3];
#pragma unroll
    for (int j = 0; j < 3; j++) {
        xr4[j] = *(const float4*)&g_xr[n * HC + col0 + 128 * j];
        we4[j] = *(const float4*)&Wel[col0 + 128 * j];
        at4[j] = *(const float4*)&attl[col0 + 128 * j];
    }

    float m[3], den[3];
    float4 acc[3];
#pragma unroll
    for (int j = 0; j < 3; j++) {
        m[j] = -1e30f;
        den[j] = 0.f;
        acc[j] = make_float4(0.f, 0.f, 0.f, 0.f);
    }

    int eid = g_csr[beg];
    int s = ei[eid];
    float eav = g_ea[eid];
    float4 xl4[3];
#pragma unroll
    for (int j = 0; j < 3; j++)
        xl4[j] = *(const float4*)&g_xl[s * HC + col0 + 128 * j];

    for (int p = beg; p < end; p++) {
        float4 cur[3];
        float ceav = eav;
#pragma unroll
        for (int j = 0; j < 3; j++) cur[j] = xl4[j];
        if (p + 1 < end) {
            eid = g_csr[p + 1];
            s = ei[eid];
            eav = g_ea[eid];
#pragma unroll
            for (int j = 0; j < 3; j++)
                xl4[j] = *(const float4*)&g_xl[s * HC + col0 + 128 * j];
        }

        float pd[3];
#pragma unroll
        for (int j = 0; j < 3; j++) {
            float gx = cur[j].x + xr4[j].x + ceav * we4[j].x;
            float gy = cur[j].y + xr4[j].y + ceav * we4[j].y;
            float gz = cur[j].z + xr4[j].z + ceav * we4[j].z;
            float gw = cur[j].w + xr4[j].w + ceav * we4[j].w;
            gx = (gx > 0.f) ? gx : 0.2f * gx;
            gy = (gy > 0.f) ? gy : 0.2f * gy;
            gz = (gz > 0.f) ? gz : 0.2f * gz;
            gw = (gw > 0.f) ? gw : 0.2f * gw;
            pd[j] = gx * at4[j].x + gy * at4[j].y + gz * at4[j].z + gw * at4[j].w;
        }
#pragma unroll
        for (int j = 0; j < 3; j++) {
            pd[j] += __shfl_xor_sync(0xffffffffu, pd[j], 1);
            pd[j] += __shfl_xor_sync(0xffffffffu, pd[j], 2);
            pd[j] += __shfl_xor_sync(0xffffffffu, pd[j], 4);
            pd[j] += __shfl_xor_sync(0xffffffffu, pd[j], 8);
        }
#pragma unroll
        for (int j = 0; j < 3; j++) {
            float a = pd[j];
            float ex;
            if (a > m[j]) {
                float sc = __expf(m[j] - a);
                den[j] *= sc;
                acc[j].x *= sc;
                acc[j].y *= sc;
                acc[j].z *= sc;
                acc[j].w *= sc;
                m[j] = a;
                ex = 1.f;
            } else {
                ex = __expf(a - m[j]);
            }
            den[j] += ex;
            acc[j].x += ex * cur[j].x;
            acc[j].y += ex * cur[j].y;
            acc[j].z += ex * cur[j].z;
            acc[j].w += ex * cur[j].w;
        }
    }

    float4 sum = make_float4(0.f, 0.f, 0.f, 0.f);
#pragma unroll
    for (int j = 0; j < 3; j++) {
        float inv = 1.f / (den[j] + 1e-16f);
        sum.x += acc[j].x * inv;
        sum.y += acc[j].y * inv;
        sum.z += acc[j].z * inv;
        sum.w += acc[j].w * inv;
    }
    sum.x += __shfl_xor_sync(0xffffffffu, sum.x, 16);
    sum.y += __shfl_xor_sync(0xffffffffu, sum.y, 16);
    sum.z += __shfl_xor_sync(0xffffffffu, sum.z, 16);
    sum.w += __shfl_xor_sync(0xffffffffu, sum.w, 16);

    if (lane < 16) {
        int c = 4 * lane;
        float4 hv = *(float4*)&g_h[n * 64 + c];
        float4 bv = *(const float4*)&bgl[c];
        float4 r;
        r.x = fmaxf(hv.x + sum.x * (1.f / 6.f) + bv.x, 0.f);
        r.y = fmaxf(hv.y + sum.y * (1.f / 6.f) + bv.y, 0.f);
        r.z = fmaxf(hv.z + sum.z * (1.f / 6.f) + bv.z, 0.f);
        r.w = fmaxf(hv.w + sum.w * (1.f / 6.f) + bv.w, 0.f);
        *(float4*)&g_h[n * 64 + c] = r;
    }
}

// ---------------- instance norm ----------------
__global__ void inorm_stats(int NP) {
    int g = blockIdx.x;
    int tid = threadIdx.x;
    int c = tid & 63, r = tid >> 6;
    float s = 0.f, s2 = 0.f;
    for (int i = r; i < NP; i += 4) {
        float v = g_h[(g * NP + i) * 64 + c];
        s += v;
        s2 += v * v;
    }
    __shared__ float sh[256], sh2[256];
    sh[tid] = s;
    sh2[tid] = s2;
    __syncthreads();
    if (r == 0) {
        float ts = sh[c] + sh[64 + c] + sh[128 + c] + sh[192 + c];
        float t2 = sh2[c] + sh2[64 + c] + sh2[128 + c] + sh2[192 + c];
        float mean = ts / NP;
        float var = fmaxf(t2 / NP - mean * mean, 0.f);
        g_mean[g * 64 + c] = mean;
        g_istd[g * 64 + c] = rsqrtf(var + 1e-5f);
    }
}
__global__ void inorm_apply(const int* __restrict__ batch, int N) {
    int idx = blockIdx.x * 256 + threadIdx.x;
    if (idx >= N * 64) return;
    int n = idx >> 6, c = idx & 63;
    int g = batch[n];
    g_h[idx] = (g_h[idx] - g_mean[g * 64 + c]) * g_istd[g * 64 + c];
}

// ---------------- final MLP head ----------------
__global__ __launch_bounds__(256) void final_kernel(
    const float* __restrict__ w_emb1, const float* __restrict__ b_emb1,
    const float* __restrict__ g1, const float* __restrict__ b1,
    const float* __restrict__ m1, const float* __restrict__ v1,
    const float* __restrict__ w_emb2, const float* __restrict__ b_emb2,
    const float* __restrict__ g2, const float* __restrict__ b2,
    const float* __restrict__ m2, const float* __restrict__ v2,
    const float* __restrict__ w_pred, const float* __restrict__ b_pred,
    float* __restrict__ out, int N) {
    __shared__ float hs[32 * 64];
    __shared__ float ws[64 * 64];
    __shared__ float zs[32 * 64];
    __shared__ float hos[32 * 64];
    __shared__ float sc1[64], sh1[64], sc2[64], sh2[64];
    int tid = threadIdx.x;
    int nbase = blockIdx.x * 32;
    if (tid < 64) {
        float s = g1[tid] * rsqrtf(v1[tid] + 1e-5f);
        sc1[tid] = s;
        sh1[tid] = b1[tid] - m1[tid] * s;
        float t = g2[tid] * rsqrtf(v2[tid] + 1e-5f);
        sc2[tid] = t;
        sh2[tid] = b2[tid] - m2[tid] * t;
    }
    for (int idx = tid; idx < 32 * 64; idx += 256) {
        int gi = nbase * 64 + idx;
        hs[idx] = (gi < N * 64) ? g_h[gi] : 0.f;
    }
    for (int idx = tid; idx < 64 * 64; idx += 256) ws[idx] = w_emb1[idx];
    __syncthreads();
    int c = tid & 63;
    int mg = (tid >> 6) * 8;
    float zv[8];
#pragma unroll
    for (int i = 0; i < 8; i++) {
        int m = mg + i;
        float acc = b_emb1[c];
#pragma unroll 4
        for (int k = 0; k < 64; k++) acc += hs[m * 64 + k] * ws[k * 64 + c];
        acc = fmaxf(acc, 0.f);
        zv[i] = acc * sc1[c] + sh1[c];
    }
    __syncthreads();
#pragma unroll
    for (int i = 0; i < 8; i++) zs[(mg + i) * 64 + c] = zv[i];
    for (int idx = tid; idx < 64 * 64; idx += 256) ws[idx] = w_emb2[idx];
    __syncthreads();
#pragma unroll
    for (int i = 0; i < 8; i++) {
        int m = mg + i;
        int n = nbase + m;
        float acc = b_emb2[c];
#pragma unroll 4
        for (int k = 0; k < 64; k++) acc += zs[m * 64 + k] * ws[k * 64 + c];
        if (n < N) out[n * 64 + c] = acc;
        hos[m * 64 + c] = acc * sc2[c] + sh2[c];
    }
    __syncthreads();
    if (tid < 32) {
        int n = nbase + tid;
        if (n < N) {
            float acc = b_pred[0];
#pragma unroll 4
            for (int k = 0; k < 64; k++) acc += hos[tid * 64 + k] * w_pred[k];
            out[N * 64 + n] = acc;
        }
    }
}

// ---------------- launch ----------------
extern "C" void kernel_launch(void* const* d_in, const int* in_sizes, int n_in,
                              void* d_out, int out_size) {
    const float* x      = (const float*)d_in[0];
    const float* pos    = (const float*)d_in[1];
    const float* w_lin1 = (const float*)d_in[2];
    const float* b_lin1 = (const float*)d_in[3];
    const float* w_e1   = (const float*)d_in[4];
    const float* b_e1   = (const float*)d_in[5];
    const float* w_e2   = (const float*)d_in[6];
    const float* b_e2   = (const float*)d_in[7];
    const float* Wl     = (const float*)d_in[8];
    const float* bl     = (const float*)d_in[9];
    const float* Wr     = (const float*)d_in[10];
    const float* br     = (const float*)d_in[11];
    const float* We     = (const float*)d_in[12];
    const float* att    = (const float*)d_in[13];
    const float* b_gat  = (const float*)d_in[14];
    const float* w_emb1 = (const float*)d_in[15];
    const float* b_emb1 = (const float*)d_in[16];
    const float* bn1_g  = (const float*)d_in[17];
    const float* bn1_b  = (const float*)d_in[18];
    const float* bn1_m  = (const float*)d_in[19];
    const float* bn1_v  = (const float*)d_in[20];
    const float* w_emb2 = (const float*)d_in[21];
    const float* b_emb2 = (const float*)d_in[22];
    const float* bn2_g  = (const float*)d_in[23];
    const float* bn2_b  = (const float*)d_in[24];
    const float* bn2_m  = (const float*)d_in[25];
    const float* bn2_v  = (const float*)d_in[26];
    const float* w_pred = (const float*)d_in[27];
    const float* b_pred = (const float*)d_in[28];
    const int*   ei     = (const int*)d_in[29];
    const int*   batch  = (const int*)d_in[30];
    float* out = (float*)d_out;

    int N = in_sizes[0] / 32;
    int E = in_sizes[29] / 2;
    int NG = 16;
    int NP = N / NG;

    ea_kernel<<<(E + 255) / 256, 256>>>(ei, pos, w_e1, b_e1, w_e2, b_e2, E);
    h0_kernel<<<(N + 3) / 4, 256>>>(x, w_lin1, b_lin1, N);
    zero_deg<<<(N + 256) / 256, 256>>>(N);
    hist_kernel<<<(E + 255) / 256, 256>>>(ei, E);
    scan_kernel<<<1, 1024>>>(N);
    scatter_kernel<<<(E + 255) / 256, 256>>>(ei, E);

    for (int i = 0; i < 4; i++) {
        const float* Wli = Wl + i * 64 * HC;
        const float* bli = bl + i * HC;
        const float* Wri = Wr + i * 64 * HC;
        const float* bri = br + i * HC;
        const float* Wei = We + i * HC;
        const float* atti = att + i * HC;
        const float* bgi = b_gat + i * 64;

        dim3 ggrid((N + 63) / 64, 12);
        gemm_tc_kernel<<<ggrid, 256>>>(Wli, bli, Wri, bri, N);
        gat_agg_kernel<<<(N + 7) / 8, 256>>>(ei, E, Wei, atti, bgi, N);
        inorm_stats<<<NG, 256>>>(NP);
        inorm_apply<<<(N * 64 + 255) / 256, 256>>>(batch, N);
    }

    final_kernel<<<(N + 31) / 32, 256>>>(w_emb1, b_emb1, bn1_g, bn1_b, bn1_m, bn1_v,
                                         w_emb2, b_emb2, bn2_g, bn2_b, bn2_m, bn2_v,
                                         w_pred, b_pred, out, N);
}

// round 4
// speedup vs baseline: 2.4437x; 1.0414x over previous
#include <cuda_runtime.h>
#include <cuda_fp16.h>
#include <math.h>
#include <stdint.h>

#define NMAX 16000
#define EMAX 400000
#define HIDC 64
#define NHEADS 6
#define HC 384
#define NGMAX 16

// ---------------- scratch ----------------
__device__ float  g_h[NMAX * HIDC];
__device__ __half g_xl[NMAX * HC];
__device__ __half g_xr[NMAX * HC];
__device__ float  g_ea[EMAX];
__device__ int    g_deg[NMAX + 1];
__device__ int    g_rowptr[NMAX + 1];
__device__ int    g_cursor[NMAX];
__device__ int    g_csr[EMAX];
__device__ float  g_mean[NGMAX * HIDC];
__device__ float  g_istd[NGMAX * HIDC];

__device__ __forceinline__ uint32_t f2tf32(float v) {
    uint32_t u;
    asm("cvt.rna.tf32.f32 %0, %1;" : "=r"(u) : "f"(v));
    return u;
}
__device__ __forceinline__ float2 h2f2(uint32_t u) {
    __half2 h = *reinterpret_cast<__half2*>(&u);
    return __half22float2(h);
}

// ---------------- edge feature MLP ----------------
__global__ void ea_kernel(const int* __restrict__ ei, const float* __restrict__ pos,
                          const float* __restrict__ w_e1, const float* __restrict__ b_e1,
                          const float* __restrict__ w_e2, const float* __restrict__ b_e2,
                          int E) {
    int e = blockIdx.x * 256 + threadIdx.x;
    if (e >= E) return;
    int s = ei[e], d = ei[E + e];
    float dx = pos[s * 3 + 0] - pos[d * 3 + 0];
    float dy = pos[s * 3 + 1] - pos[d * 3 + 1];
    float dz = pos[s * 3 + 2] - pos[d * 3 + 2];
    float ss = dx * dx + dy * dy + dz * dz;
    float ew = (ss == 0.f) ? 0.f : sqrtf(ss);
    float acc = b_e2[0];
#pragma unroll
    for (int j = 0; j < 32; j++) {
        float m = fmaxf(ew * w_e1[j] + b_e1[j], 0.f);
        acc += m * w_e2[j];
    }
    g_ea[e] = fmaxf(acc, 0.f);
}

// ---------------- h0 = x @ w_lin1 + b_lin1 ----------------
__global__ void h0_kernel(const float* __restrict__ x, const float* __restrict__ w,
                          const float* __restrict__ b, int N) {
    int tid = threadIdx.x;
    int c = tid & 63;
    int n = blockIdx.x * 4 + (tid >> 6);
    if (n >= N) return;
    float acc = b[c];
    const float* xr = x + n * 32;
#pragma unroll
    for (int k = 0; k < 32; k++) acc += xr[k] * w[k * 64 + c];
    g_h[n * 64 + c] = acc;
}

// ---------------- CSR build ----------------
__global__ void zero_deg(int N) {
    int i = blockIdx.x * 256 + threadIdx.x;
    if (i <= N) g_deg[i] = 0;
}
__global__ void hist_kernel(const int* __restrict__ ei, int E) {
    int e = blockIdx.x * 256 + threadIdx.x;
    if (e < E) atomicAdd(&g_deg[ei[E + e]], 1);
}
__global__ void scan_kernel(int N) {
    __shared__ int ss[1024];
    int tid = threadIdx.x;
    int total = N + 1;
    int per = (total + 1023) / 1024;
    int b0 = tid * per;
    int b1 = min(b0 + per, total);
    int s = 0;
    for (int i = b0; i < b1; i++) s += g_deg[i];
    ss[tid] = s;
    __syncthreads();
    for (int off = 1; off < 1024; off <<= 1) {
        int add = (tid >= off) ? ss[tid - off] : 0;
        __syncthreads();
        ss[tid] += add;
        __syncthreads();
    }
    int run = ss[tid] - s;
    for (int i = b0; i < b1; i++) {
        g_rowptr[i] = run;
        if (i < N) g_cursor[i] = run;
        run += g_deg[i];
    }
}
__global__ void scatter_kernel(const int* __restrict__ ei, int E) {
    int e = blockIdx.x * 256 + threadIdx.x;
    if (e >= E) return;
    int d = ei[E + e];
    int p = atomicAdd(&g_cursor[d], 1);
    g_csr[p] = e;
}

// ---------------- tf32 tensor-core GEMM with fused lazy instance-norm, fp16 out
#define HSTR 68
#define WSTR 76
__global__ __launch_bounds__(256) void gemm_tc_kernel(const float* __restrict__ Wl,
                                                      const float* __restrict__ bl,
                                                      const float* __restrict__ Wr,
                                                      const float* __restrict__ br,
                                                      int N, int useNorm, int NP) {
    __shared__ uint32_t hs[64 * HSTR];
    __shared__ uint32_t ws[64 * WSTR];
    int tid = threadIdx.x;
    int nbase = blockIdx.x * 64;
    int y = blockIdx.y;
    const float* W;
    const float* b;
    __half* outp;
    int colbase;
    if (y < 6) { W = Wl; b = bl; outp = g_xl; colbase = y * 64; }
    else       { W = Wr; b = br; outp = g_xr; colbase = (y - 6) * 64; }

    for (int idx = tid; idx < 64 * 64; idx += 256) {
        int m = idx >> 6, k = idx & 63;
        int n = nbase + m;
        float v = 0.f;
        if (n < N) {
            v = g_h[n * 64 + k];
            if (useNorm) {
                int g = n / NP;
                v = (v - g_mean[g * 64 + k]) * g_istd[g * 64 + k];
            }
        }
        hs[m * HSTR + k] = f2tf32(v);
    }
    for (int idx = tid; idx < 64 * 64; idx += 256) {
        int k = idx >> 6, c = idx & 63;
        ws[c * WSTR + k] = f2tf32(W[k * HC + colbase + c]);
    }
    __syncthreads();

    int w = tid >> 5, lane = tid & 31;
    int mb = (w & 3) * 16;
    int cb = (w >> 2) * 32;
    int g = lane >> 2, tig = lane & 3;

    float c0[4], c1[4], c2[4], c3[4];
#pragma unroll
    for (int nt = 0; nt < 4; nt++) { c0[nt] = c1[nt] = c2[nt] = c3[nt] = 0.f; }

#pragma unroll
    for (int k0 = 0; k0 < 64; k0 += 8) {
        uint32_t a0 = hs[(mb + g) * HSTR + k0 + tig];
        uint32_t a1 = hs[(mb + g + 8) * HSTR + k0 + tig];
        uint32_t a2 = hs[(mb + g) * HSTR + k0 + tig + 4];
        uint32_t a3 = hs[(mb + g + 8) * HSTR + k0 + tig + 4];
#pragma unroll
        for (int nt = 0; nt < 4; nt++) {
            uint32_t b0 = ws[(cb + nt * 8 + g) * WSTR + k0 + tig];
            uint32_t b1 = ws[(cb + nt * 8 + g) * WSTR + k0 + tig + 4];
            asm volatile(
                "mma.sync.aligned.m16n8k8.row.col.f32.tf32.tf32.f32 "
                "{%0,%1,%2,%3}, {%4,%5,%6,%7}, {%8,%9}, {%0,%1,%2,%3};"
                : "+f"(c0[nt]), "+f"(c1[nt]), "+f"(c2[nt]), "+f"(c3[nt])
                : "r"(a0), "r"(a1), "r"(a2), "r"(a3), "r"(b0), "r"(b1));
        }
    }

    int r0 = nbase + mb + g;
    int r1 = r0 + 8;
#pragma unroll
    for (int nt = 0; nt < 4; nt++) {
        int col = colbase + cb + nt * 8 + 2 * tig;
        float bx = b[col], by = b[col + 1];
        if (r0 < N)
            *(__half2*)&outp[r0 * HC + col] = __floats2half2_rn(c0[nt] + bx, c1[nt] + by);
        if (r1 < N)
            *(__half2*)&outp[r1 * HC + col] = __floats2half2_rn(c2[nt] + bx, c3[nt] + by);
    }
}

// ---------------- fused GATv2: logits + online softmax + aggregation (fp16 gathers)
__global__ __launch_bounds__(256) void gat_agg_kernel(const int* __restrict__ ei, int E,
                                                      const float* __restrict__ Wel,
                                                      const float* __restrict__ attl,
                                                      const float* __restrict__ bgl,
                                                      int N, int useNorm, int NP) {
    int n = blockIdx.x * 8 + (threadIdx.x >> 5);
    int lane = threadIdx.x & 31;
    if (n >= N) return;
    int beg = g_rowptr[n], end = g_rowptr[n + 1];

    int col0 = 4 * lane;  // + 128*j
    float4 xr4[3], we4[3], at4[3];
#pragma unroll
    for (int j = 0; j < 3; j++) {
        uint2 raw = *(const uint2*)&g_xr[n * HC + col0 + 128 * j];
        float2 lo = h2f2(raw.x), hi = h2f2(raw.y);
        xr4[j] = make_float4(lo.x, lo.y, hi.x, hi.y);
        we4[j] = *(const float4*)&Wel[col0 + 128 * j];
        at4[j] = *(const float4*)&attl[col0 + 128 * j];
    }

    float m[3], den[3];
    float4 acc[3];
#pragma unroll
    for (int j = 0; j < 3; j++) {
        m[j] = -1e30f;
        den[j] = 0.f;
        acc[j] = make_float4(0.f, 0.f, 0.f, 0.f);
    }

    int eid = g_csr[beg];
    int s = ei[eid];
    float eav = g_ea[eid];
    uint2 xlr[3];
#pragma unroll
    for (int j = 0; j < 3; j++)
        xlr[j] = *(const uint2*)&g_xl[s * HC + col0 + 128 * j];

    for (int p = beg; p < end; p++) {
        float4 cur[3];
        float ceav = eav;
#pragma unroll
        for (int j = 0; j < 3; j++) {
            float2 lo = h2f2(xlr[j].x), hi = h2f2(xlr[j].y);
            cur[j] = make_float4(lo.x, lo.y, hi.x, hi.y);
        }
        if (p + 1 < end) {
            eid = g_csr[p + 1];
            s = ei[eid];
            eav = g_ea[eid];
#pragma unroll
            for (int j = 0; j < 3; j++)
                xlr[j] = *(const uint2*)&g_xl[s * HC + col0 + 128 * j];
        }

        float pd[3];
#pragma unroll
        for (int j = 0; j < 3; j++) {
            float gx = cur[j].x + xr4[j].x + ceav * we4[j].x;
            float gy = cur[j].y + xr4[j].y + ceav * we4[j].y;
            float gz = cur[j].z + xr4[j].z + ceav * we4[j].z;
            float gw = cur[j].w + xr4[j].w + ceav * we4[j].w;
            gx = (gx > 0.f) ? gx : 0.2f * gx;
            gy = (gy > 0.f) ? gy : 0.2f * gy;
            gz = (gz > 0.f) ? gz : 0.2f * gz;
            gw = (gw > 0.f) ? gw : 0.2f * gw;
            pd[j] = gx * at4[j].x + gy * at4[j].y + gz * at4[j].z + gw * at4[j].w;
        }
#pragma unroll
        for (int j = 0; j < 3; j++) {
            pd[j] += __shfl_xor_sync(0xffffffffu, pd[j], 1);
            pd[j] += __shfl_xor_sync(0xffffffffu, pd[j], 2);
            pd[j] += __shfl_xor_sync(0xffffffffu, pd[j], 4);
            pd[j] += __shfl_xor_sync(0xffffffffu, pd[j], 8);
        }
#pragma unroll
        for (int j = 0; j < 3; j++) {
            float a = pd[j];
            float ex;
            if (a > m[j]) {
                float sc = __expf(m[j] - a);
                den[j] *= sc;
                acc[j].x *= sc;
                acc[j].y *= sc;
                acc[j].z *= sc;
                acc[j].w *= sc;
                m[j] = a;
                ex = 1.f;
            } else {
                ex = __expf(a - m[j]);
            }
            den[j] += ex;
            acc[j].x += ex * cur[j].x;
            acc[j].y += ex * cur[j].y;
            acc[j].z += ex * cur[j].z;
            acc[j].w += ex * cur[j].w;
        }
    }

    float4 sum = make_float4(0.f, 0.f, 0.f, 0.f);
#pragma unroll
    for (int j = 0; j < 3; j++) {
        float inv = 1.f / (den[j] + 1e-16f);
        sum.x += acc[j].x * inv;
        sum.y += acc[j].y * inv;
        sum.z += acc[j].z * inv;
        sum.w += acc[j].w * inv;
    }
    sum.x += __shfl_xor_sync(0xffffffffu, sum.x, 16);
    sum.y += __shfl_xor_sync(0xffffffffu, sum.y, 16);
    sum.z += __shfl_xor_sync(0xffffffffu, sum.z, 16);
    sum.w += __shfl_xor_sync(0xffffffffu, sum.w, 16);

    if (lane < 16) {
        int c = 4 * lane;
        float4 hv = *(float4*)&g_h[n * 64 + c];
        if (useNorm) {  // lazy instance-norm of the residual input
            int g = n / NP;
            float4 mv = *(const float4*)&g_mean[g * 64 + c];
            float4 iv = *(const float4*)&g_istd[g * 64 + c];
            hv.x = (hv.x - mv.x) * iv.x;
            hv.y = (hv.y - mv.y) * iv.y;
            hv.z = (hv.z - mv.z) * iv.z;
            hv.w = (hv.w - mv.w) * iv.w;
        }
        float4 bv = *(const float4*)&bgl[c];
        float4 r;
        r.x = fmaxf(hv.x + sum.x * (1.f / 6.f) + bv.x, 0.f);
        r.y = fmaxf(hv.y + sum.y * (1.f / 6.f) + bv.y, 0.f);
        r.z = fmaxf(hv.z + sum.z * (1.f / 6.f) + bv.z, 0.f);
        r.w = fmaxf(hv.w + sum.w * (1.f / 6.f) + bv.w, 0.f);
        *(float4*)&g_h[n * 64 + c] = r;
    }
}

// ---------------- instance-norm stats over (unnormalized) g_h ----------------
__global__ void inorm_stats(int NP) {
    int g = blockIdx.x;
    int tid = threadIdx.x;
    int c = tid & 63, r = tid >> 6;
    float s = 0.f, s2 = 0.f;
    for (int i = r; i < NP; i += 4) {
        float v = g_h[(g * NP + i) * 64 + c];
        s += v;
        s2 += v * v;
    }
    __shared__ float sh[256], sh2[256];
    sh[tid] = s;
    sh2[tid] = s2;
    __syncthreads();
    if (r == 0) {
        float ts = sh[c] + sh[64 + c] + sh[128 + c] + sh[192 + c];
        float t2 = sh2[c] + sh2[64 + c] + sh2[128 + c] + sh2[192 + c];
        float mean = ts / NP;
        float var = fmaxf(t2 / NP - mean * mean, 0.f);
        g_mean[g * 64 + c] = mean;
        g_istd[g * 64 + c] = rsqrtf(var + 1e-5f);
    }
}

// ---------------- final MLP head (normalizes h on load) ----------------
__global__ __launch_bounds__(256) void final_kernel(
    const float* __restrict__ w_emb1, const float* __restrict__ b_emb1,
    const float* __restrict__ g1, const float* __restrict__ b1,
    const float* __restrict__ m1, const float* __restrict__ v1,
    const float* __restrict__ w_emb2, const float* __restrict__ b_emb2,
    const float* __restrict__ g2, const float* __restrict__ b2,
    const float* __restrict__ m2, const float* __restrict__ v2,
    const float* __restrict__ w_pred, const float* __restrict__ b_pred,
    float* __restrict__ out, int N, int NP) {
    __shared__ float hs[32 * 64];
    __shared__ float ws[64 * 64];
    __shared__ float zs[32 * 64];
    __shared__ float hos[32 * 64];
    __shared__ float sc1[64], sh1[64], sc2[64], sh2[64];
    int tid = threadIdx.x;
    int nbase = blockIdx.x * 32;
    if (tid < 64) {
        float s = g1[tid] * rsqrtf(v1[tid] + 1e-5f);
        sc1[tid] = s;
        sh1[tid] = b1[tid] - m1[tid] * s;
        float t = g2[tid] * rsqrtf(v2[tid] + 1e-5f);
        sc2[tid] = t;
        sh2[tid] = b2[tid] - m2[tid] * t;
    }
    for (int idx = tid; idx < 32 * 64; idx += 256) {
        int m = idx >> 6, k = idx & 63;
        int n = nbase + m;
        float v = 0.f;
        if (n < N) {
            int g = n / NP;
            v = (g_h[n * 64 + k] - g_mean[g * 64 + k]) * g_istd[g * 64 + k];
        }
        hs[idx] = v;
    }
    for (int idx = tid; idx < 64 * 64; idx += 256) ws[idx] = w_emb1[idx];
    __syncthreads();
    int c = tid & 63;
    int mg = (tid >> 6) * 8;
    float zv[8];
#pragma unroll
    for (int i = 0; i < 8; i++) {
        int m = mg + i;
        float acc = b_emb1[c];
#pragma unroll 4
        for (int k = 0; k < 64; k++) acc += hs[m * 64 + k] * ws[k * 64 + c];
        acc = fmaxf(acc, 0.f);
        zv[i] = acc * sc1[c] + sh1[c];
    }
    __syncthreads();
#pragma unroll
    for (int i = 0; i < 8; i++) zs[(mg + i) * 64 + c] = zv[i];
    for (int idx = tid; idx < 64 * 64; idx += 256) ws[idx] = w_emb2[idx];
    __syncthreads();
#pragma unroll
    for (int i = 0; i < 8; i++) {
        int m = mg + i;
        int n = nbase + m;
        float acc = b_emb2[c];
#pragma unroll 4
        for (int k = 0; k < 64; k++) acc += zs[m * 64 + k] * ws[k * 64 + c];
        if (n < N) out[n * 64 + c] = acc;
        hos[m * 64 + c] = acc * sc2[c] + sh2[c];
    }
    __syncthreads();
    if (tid < 32) {
        int n = nbase + tid;
        if (n < N) {
            float acc = b_pred[0];
#pragma unroll 4
            for (int k = 0; k < 64; k++) acc += hos[tid * 64 + k] * w_pred[k];
            out[N * 64 + n] = acc;
        }
    }
}

// ---------------- launch ----------------
extern "C" void kernel_launch(void* const* d_in, const int* in_sizes, int n_in,
                              void* d_out, int out_size) {
    const float* x      = (const float*)d_in[0];
    const float* pos    = (const float*)d_in[1];
    const float* w_lin1 = (const float*)d_in[2];
    const float* b_lin1 = (const float*)d_in[3];
    const float* w_e1   = (const float*)d_in[4];
    const float* b_e1   = (const float*)d_in[5];
    const float* w_e2   = (const float*)d_in[6];
    const float* b_e2   = (const float*)d_in[7];
    const float* Wl     = (const float*)d_in[8];
    const float* bl     = (const float*)d_in[9];
    const float* Wr     = (const float*)d_in[10];
    const float* br     = (const float*)d_in[11];
    const float* We     = (const float*)d_in[12];
    const float* att    = (const float*)d_in[13];
    const float* b_gat  = (const float*)d_in[14];
    const float* w_emb1 = (const float*)d_in[15];
    const float* b_emb1 = (const float*)d_in[16];
    const float* bn1_g  = (const float*)d_in[17];
    const float* bn1_b  = (const float*)d_in[18];
    const float* bn1_m  = (const float*)d_in[19];
    const float* bn1_v  = (const float*)d_in[20];
    const float* w_emb2 = (const float*)d_in[21];
    const float* b_emb2 = (const float*)d_in[22];
    const float* bn2_g  = (const float*)d_in[23];
    const float* bn2_b  = (const float*)d_in[24];
    const float* bn2_m  = (const float*)d_in[25];
    const float* bn2_v  = (const float*)d_in[26];
    const float* w_pred = (const float*)d_in[27];
    const float* b_pred = (const float*)d_in[28];
    const int*   ei     = (const int*)d_in[29];
    float* out = (float*)d_out;

    int N = in_sizes[0] / 32;
    int E = in_sizes[29] / 2;
    int NG = 16;
    int NP = N / NG;

    ea_kernel<<<(E + 255) / 256, 256>>>(ei, pos, w_e1, b_e1, w_e2, b_e2, E);
    h0_kernel<<<(N + 3) / 4, 256>>>(x, w_lin1, b_lin1, N);
    zero_deg<<<(N + 256) / 256, 256>>>(N);
    hist_kernel<<<(E + 255) / 256, 256>>>(ei, E);
    scan_kernel<<<1, 1024>>>(N);
    scatter_kernel<<<(E + 255) / 256, 256>>>(ei, E);

    for (int i = 0; i < 4; i++) {
        const float* Wli = Wl + i * 64 * HC;
        const float* bli = bl + i * HC;
        const float* Wri = Wr + i * 64 * HC;
        const float* bri = br + i * HC;
        const float* Wei = We + i * HC;
        const float* atti = att + i * HC;
        const float* bgi = b_gat + i * 64;
        int useNorm = (i > 0) ? 1 : 0;

        dim3 ggrid((N + 63) / 64, 12);
        gemm_tc_kernel<<<ggrid, 256>>>(Wli, bli, Wri, bri, N, useNorm, NP);
        gat_agg_kernel<<<(N + 7) / 8, 256>>>(ei, E, Wei, atti, bgi, N, useNorm, NP);
        inorm_stats<<<NG, 256>>>(NP);
    }

    final_kernel<<<(N + 31) / 32, 256>>>(w_emb1, b_emb1, bn1_g, bn1_b, bn1_m, bn1_v,
                                         w_emb2, b_emb2, bn2_g, bn2_b, bn2_m, bn2_v,
                                         w_pred, b_pred, out, N, NP);
}